// round 14
// baseline (speedup 1.0000x reference)
#include <cuda_runtime.h>
#include <cstdint>
#include <math.h>

#define D_MODEL     2048
#define NUM_EXPERTS 64
#define N_TOKENS    16384
#define BM          64                  // tokens per CTA
#define BK          32                  // K per chunk
#define NCHUNK      (D_MODEL / BK)      // 64
#define THREADS     256                 // 8 warps; warp tile = 16 tokens x 32 experts
#define NSTAGE      3
#define ROWB        160                 // bytes per smem row (128 data + 32 pad) - conflict-free
#define GAP_THRESH  3e-4f
#define LSTRIDE     65

// stage = A-raw fp32 tile (64 x 160) then B-plane tile (64 x 160)
#define SM_BIAS     0
#define SM_BUF      256
#define BOFF        (BM * ROWB)                   // 10240
#define STAGEB      (2 * BOFF)                    // 20480
#define SM_FLAGS    (SM_BUF + 16640)              // after L[64][65] floats
#define SMEM_TOTAL  (SM_BUF + NSTAGE * STAGEB)    // 61696 -> 3 CTAs/SM

// pre-converted W planes: [chunk][expert][pair] = uint2{plane1 bf16x2, plane2 bf16x2}
__device__ uint2 gWB[NCHUNK * NUM_EXPERTS * 16];

// ---------------------------------------------------------------------------
static __device__ __forceinline__ uint32_t bf16x2_rn(float lo, float hi) {
    uint32_t r;
    asm("cvt.rn.bf16x2.f32 %0, %1, %2;" : "=r"(r) : "f"(hi), "f"(lo));
    return r;
}
static __device__ __forceinline__ float bf16_lo_f(uint32_t u) {
    return __uint_as_float(u << 16);
}
static __device__ __forceinline__ float bf16_hi_f(uint32_t u) {
    return __uint_as_float(u & 0xffff0000u);
}
static __device__ __forceinline__ uint2 split_pair(float x, float y) {
    uint32_t b1 = bf16x2_rn(x, y);
    float r1x = x - bf16_lo_f(b1);
    float r1y = y - bf16_hi_f(b1);
    uint32_t b2 = bf16x2_rn(r1x, r1y);
    return make_uint2(b1, b2);
}
static __device__ __forceinline__ uint2 lds_pair(const char* base, int row, int p) {
    return *(const uint2*)(base + row * ROWB + p * 8);
}
static __device__ __forceinline__ float2 lds_f2(const char* base, int row, int p) {
    return *(const float2*)(base + row * ROWB + p * 8);
}
static __device__ __forceinline__ void mma_bf16(float* d,
                                                uint32_t a0, uint32_t a1,
                                                uint32_t a2, uint32_t a3,
                                                uint32_t b0, uint32_t b1) {
    asm volatile(
        "mma.sync.aligned.m16n8k16.row.col.f32.bf16.bf16.f32 "
        "{%0,%1,%2,%3}, {%4,%5,%6,%7}, {%8,%9}, {%0,%1,%2,%3};"
        : "+f"(d[0]), "+f"(d[1]), "+f"(d[2]), "+f"(d[3])
        : "r"(a0), "r"(a1), "r"(a2), "r"(a3), "r"(b0), "r"(b1));
}

#define CP_ASYNC16(dst, gsrc) \
    asm volatile("cp.async.cg.shared.global [%0], [%1], 16;" \
                 :: "r"(dst), "l"(gsrc) : "memory")
#define CP_COMMIT()  asm volatile("cp.async.commit_group;" ::: "memory")
#define CP_WAIT(n)   asm volatile("cp.async.wait_group %0;" :: "n"(n) : "memory")

static __device__ __forceinline__ uint32_t smem_u32(const void* p) {
    uint32_t a;
    asm("{ .reg .u64 t; cvta.to.shared.u64 t, %1; cvt.u32.u64 %0, t; }"
        : "=r"(a) : "l"(p));
    return a;
}

// ---------------------------------------------------------------------------
// Kernel 0: convert W -> bf16 plane pairs in [chunk][expert][pair] order
// ---------------------------------------------------------------------------
__global__ void conv_w(const float* __restrict__ W) {
    int pi = blockIdx.x * 256 + threadIdx.x;          // stride over 65536 pairs
    #pragma unroll
    for (int it = 0; it < 4; it++, pi += 16384) {
        int p = pi & 15, e = (pi >> 4) & 63, c = pi >> 10;
        int k = c * BK + 2 * p;
        gWB[pi] = split_pair(W[e * D_MODEL + k], W[e * D_MODEL + k + 1]);
    }
}

// ---------------------------------------------------------------------------
// Kernel 1: cp.async-pipelined bf16x3 GEMM (batched fragment loads) +
// top-4 gap test + in-CTA fp64 refinement
// ---------------------------------------------------------------------------
__global__ __launch_bounds__(THREADS)
void router_fused(const float* __restrict__ X, const float* __restrict__ W,
                  const float* __restrict__ bias, float* __restrict__ out) {
    extern __shared__ __align__(16) char smem[];
    float* bias_s = (float*)(smem + SM_BIAS);
    char*  bufs   = smem + SM_BUF;
    const uint32_t sbase = smem_u32(bufs);

    const int tid  = threadIdx.x;
    const int wid  = tid >> 5;
    const int lane = tid & 31;
    const int grp  = lane >> 2;     // 0..7
    const int qid  = lane & 3;      // 0..3
    const int token0 = blockIdx.x * BM;
    const int r0 = (wid >> 1) * 16 + grp;   // token rows r0, r0+8
    const int eb = (wid & 1) * 32;          // expert half

    if (tid < NUM_EXPERTS) bias_s[tid] = bias[tid];

    // per-thread cp.async slots: 2 units A + 2 units B per chunk
    uint32_t smoff[2];
    unsigned long long gA[2], gB[2];
    #pragma unroll
    for (int j = 0; j < 2; j++) {
        int g = j * THREADS + tid;            // 0..511
        int row = g >> 3, u = g & 7;
        smoff[j] = (uint32_t)(row * ROWB + u * 16);
        gA[j] = (unsigned long long)__cvta_generic_to_global(
                    X + (size_t)(token0 + row) * D_MODEL + u * 4);
        gB[j] = (unsigned long long)__cvta_generic_to_global(
                    (const char*)gWB + (size_t)row * 128 + u * 16);
    }

    float acc[4][4];
    #pragma unroll
    for (int n = 0; n < 4; n++)
        #pragma unroll
        for (int r = 0; r < 4; r++) acc[n][r] = 0.0f;

    // prologue: issue chunks 0,1
    #pragma unroll
    for (int c = 0; c < 2; c++) {
        uint32_t st = sbase + c * STAGEB;
        #pragma unroll
        for (int j = 0; j < 2; j++) CP_ASYNC16(st + smoff[j], gA[j] + (size_t)c * 128);
        #pragma unroll
        for (int j = 0; j < 2; j++) CP_ASYNC16(st + BOFF + smoff[j], gB[j] + (size_t)c * 8192);
        CP_COMMIT();
    }

    int stage = 0;
    #pragma unroll 1
    for (int c = 0; c < NCHUNK; c++) {
        CP_WAIT(1);            // chunk c's group complete
        __syncthreads();       // all threads past compute of chunk c-1

        if (c + 2 < NCHUNK) {  // issue chunk c+2 into stage (c+2)%3 (= (c-1)%3)
            const int cn = c + 2;
            uint32_t st = sbase + ((stage + 2) % NSTAGE) * STAGEB;
            #pragma unroll
            for (int j = 0; j < 2; j++) CP_ASYNC16(st + smoff[j], gA[j] + (size_t)cn * 128);
            #pragma unroll
            for (int j = 0; j < 2; j++) CP_ASYNC16(st + BOFF + smoff[j], gB[j] + (size_t)cn * 8192);
        }
        CP_COMMIT();

        const char* As = bufs + stage * STAGEB;   // raw fp32
        const char* Bs = As + BOFF;               // bf16 planes
        #pragma unroll
        for (int s8 = 0; s8 < 2; s8++) {
            const int p0 = s8 * 8 + qid;
            // batch ALL loads first (independent LDS, long dependency distance)
            float2 ar0 = lds_f2(As, r0,     p0);
            float2 ar1 = lds_f2(As, r0 + 8, p0);
            float2 ar2 = lds_f2(As, r0,     p0 + 4);
            float2 ar3 = lds_f2(As, r0 + 8, p0 + 4);
            uint2 b0[4], b1[4];
            #pragma unroll
            for (int n = 0; n < 4; n++) {
                const int e = eb + n * 8 + grp;
                b0[n] = lds_pair(Bs, e, p0);
                b1[n] = lds_pair(Bs, e, p0 + 4);
            }
            // convert A (overlaps with B loads in flight)
            uint2 a0 = split_pair(ar0.x, ar0.y);
            uint2 a1 = split_pair(ar1.x, ar1.y);
            uint2 a2 = split_pair(ar2.x, ar2.y);
            uint2 a3 = split_pair(ar3.x, ar3.y);
            // MMA burst
            #pragma unroll
            for (int n = 0; n < 4; n++) {
                mma_bf16(acc[n], a0.x, a1.x, a2.x, a3.x, b0[n].x, b1[n].x); // 1*1
                mma_bf16(acc[n], a0.x, a1.x, a2.x, a3.x, b0[n].y, b1[n].y); // 1*2
                mma_bf16(acc[n], a0.y, a1.y, a2.y, a3.y, b0[n].x, b1[n].x); // 2*1
            }
        }
        stage = (stage + 1 == NSTAGE) ? 0 : stage + 1;
    }
    CP_WAIT(0);
    __syncthreads();

    // ------------------------------------------------------------------
    // epilogue: stage logits, per-token top-4 scan, gap test
    // ------------------------------------------------------------------
    float* L     = (float*)(smem + SM_BUF);      // L[t][e] at t*LSTRIDE+e
    int*   flags = (int*)(smem + SM_FLAGS);

    #pragma unroll
    for (int n = 0; n < 4; n++) {
        int e0 = eb + n * 8 + 2 * qid;
        L[r0 * LSTRIDE + e0]           = acc[n][0];
        L[r0 * LSTRIDE + e0 + 1]       = acc[n][1];
        L[(r0 + 8) * LSTRIDE + e0]     = acc[n][2];
        L[(r0 + 8) * LSTRIDE + e0 + 1] = acc[n][3];
    }
    if (tid == 0) flags[0] = 0;
    __syncthreads();

    if (tid < BM) {
        const float* Lr = L + tid * LSTRIDE;
        float tv0 = -1e30f, tv1 = -1e30f, tv2 = -1e30f, tv3 = -1e30f;
        int   ti0 = 0, ti1 = 0, ti2 = 0, ti3 = 0;
        #pragma unroll
        for (int e = 0; e < NUM_EXPERTS; e++) {
            float v = Lr[e] + bias_s[e];
            if (v > tv0) {
                tv3 = tv2; ti3 = ti2; tv2 = tv1; ti2 = ti1;
                tv1 = tv0; ti1 = ti0; tv0 = v;  ti0 = e;
            } else if (v > tv1) {
                tv3 = tv2; ti3 = ti2; tv2 = tv1; ti2 = ti1; tv1 = v; ti1 = e;
            } else if (v > tv2) {
                tv3 = tv2; ti3 = ti2; tv2 = v;  ti2 = e;
            } else if (v > tv3) {
                tv3 = v; ti3 = e;
            }
        }
        const int token = token0 + tid;
        if ((tv0 - tv1) < GAP_THRESH || (tv1 - tv2) < GAP_THRESH) {
            int idx = atomicAdd(&flags[0], 1);
            int* rec = &flags[1 + idx * 5];
            rec[0] = token; rec[1] = ti0; rec[2] = ti1; rec[3] = ti2; rec[4] = ti3;
        } else {
            float r  = expf(tv1 - tv0);
            out[token * 2 + 0] = 1.0f / (1.0f + r);
            out[token * 2 + 1] = r / (1.0f + r);
            out[N_TOKENS * 2 + token * 2 + 0] = (float)ti0;
            out[N_TOKENS * 2 + token * 2 + 1] = (float)ti1;
        }
    }
    __syncthreads();

    // ------------------------------------------------------------------
    // in-CTA fp64 refinement of flagged tokens (one warp per record)
    // ------------------------------------------------------------------
    const int nrec = flags[0];
    for (int r = wid; r < nrec; r += 8) {
        const int* rec = &flags[1 + r * 5];
        const int token = rec[0];
        const float* xr = X + (size_t)token * D_MODEL;
        const float* w0 = W + (size_t)rec[1] * D_MODEL;
        const float* w1 = W + (size_t)rec[2] * D_MODEL;
        const float* w2 = W + (size_t)rec[3] * D_MODEL;
        const float* w3 = W + (size_t)rec[4] * D_MODEL;

        double a0[4] = {0, 0, 0, 0}, a1[4] = {0, 0, 0, 0};
        #pragma unroll 4
        for (int k = lane; k < D_MODEL; k += 64) {
            double x0 = (double)xr[k], x1 = (double)xr[k + 32];
            a0[0] += x0 * (double)w0[k];  a1[0] += x1 * (double)w0[k + 32];
            a0[1] += x0 * (double)w1[k];  a1[1] += x1 * (double)w1[k + 32];
            a0[2] += x0 * (double)w2[k];  a1[2] += x1 * (double)w2[k + 32];
            a0[3] += x0 * (double)w3[k];  a1[3] += x1 * (double)w3[k + 32];
        }
        double lv[4];
        #pragma unroll
        for (int cc = 0; cc < 4; cc++) {
            double s = a0[cc] + a1[cc];
            #pragma unroll
            for (int off = 16; off; off >>= 1)
                s += __shfl_down_sync(0xffffffffu, s, off);
            lv[cc] = s + (double)bias_s[rec[1 + cc]];
        }
        if (lane == 0) {
            int ei[4] = {rec[1], rec[2], rec[3], rec[4]};
            #pragma unroll
            for (int i = 1; i < 4; i++) {
                double v = lv[i]; int id = ei[i];
                int j = i - 1;
                while (j >= 0 && (lv[j] < v || (lv[j] == v && ei[j] > id))) {
                    lv[j + 1] = lv[j]; ei[j + 1] = ei[j]; j--;
                }
                lv[j + 1] = v; ei[j + 1] = id;
            }
            double rr = exp(lv[1] - lv[0]);
            out[token * 2 + 0] = (float)(1.0 / (1.0 + rr));
            out[token * 2 + 1] = (float)(rr / (1.0 + rr));
            out[N_TOKENS * 2 + token * 2 + 0] = (float)ei[0];
            out[N_TOKENS * 2 + token * 2 + 1] = (float)ei[1];
        }
    }
}

// ---------------------------------------------------------------------------
extern "C" void kernel_launch(void* const* d_in, const int* in_sizes, int n_in,
                              void* d_out, int out_size) {
    const float* X = (const float*)d_in[0];   // [4, 4096, 2048]
    const float* W = (const float*)d_in[1];   // [64, 2048]
    const float* b = (const float*)d_in[2];   // [64]
    float* out = (float*)d_out;

    static int configured = 0;
    if (!configured) {
        cudaFuncSetAttribute(router_fused,
                             cudaFuncAttributeMaxDynamicSharedMemorySize, SMEM_TOTAL);
        configured = 1;
    }
    conv_w<<<64, 256>>>(W);
    router_fused<<<N_TOKENS / BM, THREADS, SMEM_TOTAL>>>(X, W, b, out);
}